// round 5
// baseline (speedup 1.0000x reference)
#include <cuda_runtime.h>
#include <cuda_bf16.h>
#include <cstddef>

#define N_USERS 200000
#define N_ITEMS 100000
#define N_NODES 300000
#define DIM     64
#define N_EDGES 1200000

// bf16 copy of emb and bf16 accumulator (128 B per node each; 38.4 MB each)
__device__ uint4 g_embh[(size_t)N_NODES * 8];
__device__ uint4 g_acc [(size_t)N_NODES * 8];
__device__ int   g_identity;

__device__ __forceinline__ float sigf(float x) {
    return 1.0f / (1.0f + __expf(-x));
}
__device__ __forceinline__ unsigned pack_bf2(float a, float b) {
    __nv_bfloat162 p = __floats2bfloat162_rn(a, b);
    return reinterpret_cast<unsigned&>(p);
}
__device__ __forceinline__ float2 unpack_bf2(unsigned u) {
    __nv_bfloat162 p = reinterpret_cast<__nv_bfloat162&>(u);
    return __bfloat1622float2(p);
}
__device__ __forceinline__ unsigned mul_bf2(unsigned a, unsigned b) {
    __nv_bfloat162 pa = reinterpret_cast<__nv_bfloat162&>(a);
    __nv_bfloat162 pb = reinterpret_cast<__nv_bfloat162&>(b);
    __nv_bfloat162 r = __hmul2(pa, pb);
    return reinterpret_cast<unsigned&>(r);
}

// ---------------------------------------------------------------------------
// seedA (critical path): g_embh[n] = bf16(emb[n]); g_acc[n] = bf16(2*emb[n]).
// 8 threads/node, uint4 stores. Last block: filt == I check (gates epi).
// ---------------------------------------------------------------------------
__global__ void seedA_kernel(const float4* __restrict__ ue4,
                             const float4* __restrict__ ie4,
                             const float*  __restrict__ filt) {
    if (blockIdx.x == gridDim.x - 1) {
        __shared__ int ok;
        if (threadIdx.x == 0) ok = 1;
        __syncthreads();
        for (int i = threadIdx.x; i < DIM * DIM; i += blockDim.x) {
            int r = i >> 6, c = i & 63;
            float expect = (r == c) ? 1.0f : 0.0f;
            if (filt[i] != expect) atomicAnd(&ok, 0);
        }
        __syncthreads();
        if (threadIdx.x == 0) g_identity = ok;
        return;
    }
    unsigned idx = blockIdx.x * blockDim.x + threadIdx.x;
    unsigned n = idx >> 3;
    unsigned c = idx & 7u;
    if (n >= (unsigned)N_NODES) return;

    const float4* src = (n < N_USERS) ? (ue4 + (size_t)n * 16)
                                      : (ie4 + (size_t)(n - N_USERS) * 16);
    float4 e0 = __ldg(src + 2 * c);
    float4 e1 = __ldg(src + 2 * c + 1);

    uint4 eh;
    eh.x = pack_bf2(e0.x, e0.y);
    eh.y = pack_bf2(e0.z, e0.w);
    eh.z = pack_bf2(e1.x, e1.y);
    eh.w = pack_bf2(e1.z, e1.w);
    g_embh[(size_t)n * 8 + c] = eh;

    uint4 a2;
    a2.x = pack_bf2(2.f * e0.x, 2.f * e0.y);
    a2.y = pack_bf2(2.f * e0.z, 2.f * e0.w);
    a2.z = pack_bf2(2.f * e1.x, 2.f * e1.y);
    a2.w = pack_bf2(2.f * e1.z, 2.f * e1.w);
    g_acc[(size_t)n * 8 + c] = a2;
}

// ---------------------------------------------------------------------------
// seedB (side stream, off critical path): out[n, 0:64] = emb[n] (f32 exact).
// 16 threads/node, float4 lanes.
// ---------------------------------------------------------------------------
__global__ void seedB_kernel(const float4* __restrict__ ue4,
                             const float4* __restrict__ ie4,
                             float4*       __restrict__ out4) {
    unsigned idx = blockIdx.x * blockDim.x + threadIdx.x;
    unsigned n = idx >> 4;
    unsigned c = idx & 15u;
    if (n >= (unsigned)N_NODES) return;
    float4 e = (n < N_USERS) ? __ldg(ue4 + (size_t)n * 16 + c)
                             : __ldg(ie4 + (size_t)(n - N_USERS) * 16 + c);
    out4[(size_t)n * 32 + c] = e;
}

// ---------------------------------------------------------------------------
// Edge scatter: acc[row] -= val * embh[col]   (bf16x2 vector L2 reduction)
// 8 threads/edge, 16 B per thread.
// ---------------------------------------------------------------------------
__global__ void edge_kernel(const int*   __restrict__ rows,
                            const int*   __restrict__ cols,
                            const float* __restrict__ vals) {
    unsigned idx = blockIdx.x * blockDim.x + threadIdx.x;
    if (idx >= (unsigned)N_EDGES * 8u) return;
    unsigned e = idx >> 3;
    unsigned c = idx & 7u;

    int   col = __ldg(cols + e);
    int   row = __ldg(rows + e);
    float v   = -__ldg(vals + e);          // negated: acc computes 2e - agg
    unsigned vv = pack_bf2(v, v);

    uint4 x = __ldg(&g_embh[(size_t)col * 8 + c]);
    x.x = mul_bf2(x.x, vv);
    x.y = mul_bf2(x.y, vv);
    x.z = mul_bf2(x.z, vv);
    x.w = mul_bf2(x.w, vv);

    uint4* dst = &g_acc[(size_t)row * 8 + c];
    asm volatile("red.global.add.noftz.v4.bf16x2 [%0], {%1, %2, %3, %4};"
                 :: "l"(dst), "r"(x.x), "r"(x.y), "r"(x.z), "r"(x.w)
                 : "memory");
}

// ---------------------------------------------------------------------------
// Epilogue: acc holds t = 2e - agg (bf16). out[n,64:128] = sigmoid(t), or
// sigmoid(t @ filt) fallback. 8 threads/node; blockDim 256 (32 nodes/block).
// ---------------------------------------------------------------------------
__global__ void epi_kernel(const float* __restrict__ filt,
                           float4*      __restrict__ out4) {
    unsigned idx = blockIdx.x * blockDim.x + threadIdx.x;
    unsigned n = idx >> 3;
    unsigned c = idx & 7u;
    bool active = (n < (unsigned)N_NODES);

    uint4 a = make_uint4(0, 0, 0, 0);
    if (active) a = g_acc[(size_t)n * 8 + c];
    float2 t0 = unpack_bf2(a.x);
    float2 t1 = unpack_bf2(a.y);
    float2 t2 = unpack_bf2(a.z);
    float2 t3 = unpack_bf2(a.w);

    if (g_identity) {
        if (active) {
            float4 h0 = make_float4(sigf(t0.x), sigf(t0.y), sigf(t1.x), sigf(t1.y));
            float4 h1 = make_float4(sigf(t2.x), sigf(t2.y), sigf(t3.x), sigf(t3.y));
            out4[(size_t)n * 32 + 16 + c * 2]     = h0;
            out4[(size_t)n * 32 + 16 + c * 2 + 1] = h1;
        }
    } else {
        __shared__ float ts[32][DIM];
        unsigned ln = threadIdx.x >> 3;
        float* tr = ts[ln] + c * 8;
        tr[0] = t0.x; tr[1] = t0.y; tr[2] = t1.x; tr[3] = t1.y;
        tr[4] = t2.x; tr[5] = t2.y; tr[6] = t3.x; tr[7] = t3.y;
        __syncthreads();
        if (active) {
            const float* trow = ts[ln];
            float s[8] = {0.f};
            #pragma unroll 8
            for (int k = 0; k < DIM; k++) {
                float tk = trow[k];
                const float* frow = filt + (size_t)k * DIM + c * 8;
                #pragma unroll
                for (int j = 0; j < 8; j++) s[j] += tk * frow[j];
            }
            float4 h0 = make_float4(sigf(s[0]), sigf(s[1]), sigf(s[2]), sigf(s[3]));
            float4 h1 = make_float4(sigf(s[4]), sigf(s[5]), sigf(s[6]), sigf(s[7]));
            out4[(size_t)n * 32 + 16 + c * 2]     = h0;
            out4[(size_t)n * 32 + 16 + c * 2 + 1] = h1;
        }
    }
}

// ---------------------------------------------------------------------------
// Launch: seedB (out-emb copy) forks onto a side stream and overlaps the
// L2-bound edge phase; main stream runs seedA -> edge -> epi, then joins.
// Stream/events are created once (host-side objects, no device allocations).
// ---------------------------------------------------------------------------
extern "C" void kernel_launch(void* const* d_in, const int* in_sizes, int n_in,
                              void* d_out, int out_size) {
    const int*   rows = (const int*)  d_in[0];
    const int*   cols = (const int*)  d_in[1];
    const float* vals = (const float*)d_in[2];
    const float* ue   = (const float*)d_in[3];
    const float* ie   = (const float*)d_in[4];
    const float* filt = (const float*)d_in[5];
    float4*      out4 = (float4*)d_out;

    static cudaStream_t s_side = nullptr;
    static cudaEvent_t  ev_fork = nullptr, ev_join = nullptr;
    if (s_side == nullptr) {
        cudaStreamCreateWithFlags(&s_side, cudaStreamNonBlocking);
        cudaEventCreateWithFlags(&ev_fork, cudaEventDisableTiming);
        cudaEventCreateWithFlags(&ev_join, cudaEventDisableTiming);
    }

    // Fork: side stream inherits capture from the main (default) stream.
    cudaEventRecord(ev_fork, 0);
    cudaStreamWaitEvent(s_side, ev_fork, 0);

    const unsigned seedB_threads = (unsigned)N_NODES * 16u;      // 4.8M
    seedB_kernel<<<(seedB_threads + 255) / 256, 256, 0, s_side>>>(
        (const float4*)ue, (const float4*)ie, out4);
    cudaEventRecord(ev_join, s_side);

    // Main stream: critical path.
    const unsigned seedA_threads = (unsigned)N_NODES * 8u;       // 2.4M
    const unsigned seedA_blocks  = (seedA_threads + 255) / 256;
    seedA_kernel<<<seedA_blocks + 1, 256>>>(
        (const float4*)ue, (const float4*)ie, filt);

    const unsigned edge_threads = (unsigned)N_EDGES * 8u;        // 9.6M
    edge_kernel<<<(edge_threads + 255) / 256, 256>>>(rows, cols, vals);

    const unsigned epi_threads = (unsigned)N_NODES * 8u;         // 2.4M
    epi_kernel<<<(epi_threads + 255) / 256, 256>>>(filt, out4);

    // Join: main stream completion implies seedB done.
    cudaStreamWaitEvent(0, ev_join, 0);
}

// round 6
// speedup vs baseline: 1.3339x; 1.3339x over previous
#include <cuda_runtime.h>
#include <cuda_bf16.h>
#include <cstddef>

#define N_USERS 200000
#define N_ITEMS 100000
#define N_NODES 300000
#define DIM     64
#define N_EDGES 1200000

// bf16 copy of emb and bf16 accumulator (128 B per node each; 38.4 MB each)
__device__ uint4 g_embh[(size_t)N_NODES * 8];
__device__ uint4 g_acc [(size_t)N_NODES * 8];
__device__ int   g_identity;

__device__ __forceinline__ float sigf_exact(float x) {
    return 1.0f / (1.0f + __expf(-x));
}
// Odd-polynomial sigmoid: rel err < 3e-4 for |t| <= 1; exact fallback beyond.
__device__ __forceinline__ float sigf(float t) {
    if (__builtin_expect(fabsf(t) < 1.0f, 1)) {
        float t2 = t * t;
        float p  = fmaf(t2, 1.0f / 480.0f, -1.0f / 48.0f);
        p        = fmaf(t2, p, 0.25f);
        return fmaf(t, p, 0.5f);
    }
    return sigf_exact(t);
}
__device__ __forceinline__ unsigned pack_bf2(float a, float b) {
    __nv_bfloat162 p = __floats2bfloat162_rn(a, b);
    return reinterpret_cast<unsigned&>(p);
}
__device__ __forceinline__ float2 unpack_bf2(unsigned u) {
    __nv_bfloat162 p = reinterpret_cast<__nv_bfloat162&>(u);
    return __bfloat1622float2(p);
}
__device__ __forceinline__ unsigned mul_bf2(unsigned a, unsigned b) {
    __nv_bfloat162 pa = reinterpret_cast<__nv_bfloat162&>(a);
    __nv_bfloat162 pb = reinterpret_cast<__nv_bfloat162&>(b);
    __nv_bfloat162 r = __hmul2(pa, pb);
    return reinterpret_cast<unsigned&>(r);
}

// ---------------------------------------------------------------------------
// Seed: out[n,0:64] = emb (f32); g_embh[n] = bf16(emb); g_acc[n] = bf16(2*emb).
// 16 threads/node (float4 lanes). Last block checks filt == I.
// ---------------------------------------------------------------------------
__global__ void seed_kernel(const float4* __restrict__ ue4,
                            const float4* __restrict__ ie4,
                            const float*  __restrict__ filt,
                            float4*       __restrict__ out4) {
    if (blockIdx.x == gridDim.x - 1) {
        __shared__ int ok;
        if (threadIdx.x == 0) ok = 1;
        __syncthreads();
        for (int i = threadIdx.x; i < DIM * DIM; i += blockDim.x) {
            int r = i >> 6, c = i & 63;
            float expect = (r == c) ? 1.0f : 0.0f;
            if (filt[i] != expect) atomicAnd(&ok, 0);
        }
        __syncthreads();
        if (threadIdx.x == 0) g_identity = ok;
        return;
    }
    unsigned idx = blockIdx.x * blockDim.x + threadIdx.x;
    unsigned n = idx >> 4;
    unsigned c = idx & 15u;
    if (n >= (unsigned)N_NODES) return;

    float4 e = (n < N_USERS) ? __ldg(ue4 + (size_t)n * 16 + c)
                             : __ldg(ie4 + (size_t)(n - N_USERS) * 16 + c);
    out4[(size_t)n * 32 + c] = e;

    uint2 eh;
    eh.x = pack_bf2(e.x, e.y);
    eh.y = pack_bf2(e.z, e.w);
    reinterpret_cast<uint2*>(g_embh)[(size_t)n * 16 + c] = eh;

    uint2 a2;
    a2.x = pack_bf2(2.f * e.x, 2.f * e.y);
    a2.y = pack_bf2(2.f * e.z, 2.f * e.w);
    reinterpret_cast<uint2*>(g_acc)[(size_t)n * 16 + c] = a2;
}

// ---------------------------------------------------------------------------
// Edge scatter: acc[row] -= val * embh[col]   (bf16x2 vector L2 reduction)
// 8 threads/edge; each thread handles 8 bf16 values (16 B).
// ---------------------------------------------------------------------------
__global__ void edge_kernel(const int*   __restrict__ rows,
                            const int*   __restrict__ cols,
                            const float* __restrict__ vals) {
    unsigned idx = blockIdx.x * blockDim.x + threadIdx.x;
    if (idx >= (unsigned)N_EDGES * 8u) return;
    unsigned e = idx >> 3;
    unsigned c = idx & 7u;

    int   col = __ldg(cols + e);
    int   row = __ldg(rows + e);
    float v   = -__ldg(vals + e);          // negated: acc computes 2e - agg
    unsigned vv = pack_bf2(v, v);

    uint4 x = __ldg(&g_embh[(size_t)col * 8 + c]);
    x.x = mul_bf2(x.x, vv);
    x.y = mul_bf2(x.y, vv);
    x.z = mul_bf2(x.z, vv);
    x.w = mul_bf2(x.w, vv);

    uint4* dst = &g_acc[(size_t)row * 8 + c];
    asm volatile("red.global.add.noftz.v4.bf16x2 [%0], {%1, %2, %3, %4};"
                 :: "l"(dst), "r"(x.x), "r"(x.y), "r"(x.z), "r"(x.w)
                 : "memory");
}

// ---------------------------------------------------------------------------
// Epilogue: acc holds t = 2e - agg (bf16). out[n,64:128] = sigmoid(t)
// (polynomial, no MUFU) or sigmoid(t @ filt) fallback.
// 8 threads/node; blockDim 256 (32 nodes/block).
// ---------------------------------------------------------------------------
__global__ void epi_kernel(const float* __restrict__ filt,
                           float4*      __restrict__ out4) {
    unsigned idx = blockIdx.x * blockDim.x + threadIdx.x;
    unsigned n = idx >> 3;
    unsigned c = idx & 7u;
    bool active = (n < (unsigned)N_NODES);

    uint4 a = make_uint4(0, 0, 0, 0);
    if (active) a = g_acc[(size_t)n * 8 + c];
    float2 t0 = unpack_bf2(a.x);
    float2 t1 = unpack_bf2(a.y);
    float2 t2 = unpack_bf2(a.z);
    float2 t3 = unpack_bf2(a.w);

    if (g_identity) {
        if (active) {
            float4 h0 = make_float4(sigf(t0.x), sigf(t0.y), sigf(t1.x), sigf(t1.y));
            float4 h1 = make_float4(sigf(t2.x), sigf(t2.y), sigf(t3.x), sigf(t3.y));
            out4[(size_t)n * 32 + 16 + c * 2]     = h0;
            out4[(size_t)n * 32 + 16 + c * 2 + 1] = h1;
        }
    } else {
        __shared__ float ts[32][DIM];
        unsigned ln = threadIdx.x >> 3;
        float* tr = ts[ln] + c * 8;
        tr[0] = t0.x; tr[1] = t0.y; tr[2] = t1.x; tr[3] = t1.y;
        tr[4] = t2.x; tr[5] = t2.y; tr[6] = t3.x; tr[7] = t3.y;
        __syncthreads();
        if (active) {
            const float* trow = ts[ln];
            float s[8] = {0.f};
            #pragma unroll 8
            for (int k = 0; k < DIM; k++) {
                float tk = trow[k];
                const float* frow = filt + (size_t)k * DIM + c * 8;
                #pragma unroll
                for (int j = 0; j < 8; j++) s[j] += tk * frow[j];
            }
            float4 h0 = make_float4(sigf_exact(s[0]), sigf_exact(s[1]),
                                    sigf_exact(s[2]), sigf_exact(s[3]));
            float4 h1 = make_float4(sigf_exact(s[4]), sigf_exact(s[5]),
                                    sigf_exact(s[6]), sigf_exact(s[7]));
            out4[(size_t)n * 32 + 16 + c * 2]     = h0;
            out4[(size_t)n * 32 + 16 + c * 2 + 1] = h1;
        }
    }
}

// ---------------------------------------------------------------------------
// Launch (single stream — the Round-5 fork/join regressed; reverted)
// ---------------------------------------------------------------------------
extern "C" void kernel_launch(void* const* d_in, const int* in_sizes, int n_in,
                              void* d_out, int out_size) {
    const int*   rows = (const int*)  d_in[0];
    const int*   cols = (const int*)  d_in[1];
    const float* vals = (const float*)d_in[2];
    const float* ue   = (const float*)d_in[3];
    const float* ie   = (const float*)d_in[4];
    const float* filt = (const float*)d_in[5];
    float4*      out4 = (float4*)d_out;

    const unsigned seed_threads = (unsigned)N_NODES * 16u;       // 4.8M
    const unsigned seed_blocks  = (seed_threads + 255) / 256;
    seed_kernel<<<seed_blocks + 1, 256>>>(
        (const float4*)ue, (const float4*)ie, filt, out4);

    const unsigned edge_threads = (unsigned)N_EDGES * 8u;        // 9.6M
    edge_kernel<<<(edge_threads + 255) / 256, 256>>>(rows, cols, vals);

    const unsigned epi_threads = (unsigned)N_NODES * 8u;         // 2.4M
    epi_kernel<<<(epi_threads + 255) / 256, 256>>>(filt, out4);
}

// round 8
// speedup vs baseline: 1.3602x; 1.0197x over previous
#include <cuda_runtime.h>
#include <cuda_fp16.h>
#include <cstddef>

#define N_USERS 200000
#define N_ITEMS 100000
#define N_NODES 300000
#define DIM     64
#define N_EDGES 1200000

#define SCALE     256.0f
#define INV_SCALE (1.0f / 256.0f)

// fp8(e4m3) copy of emb*256 (64 B/node, 19.2 MB) and half accumulator holding
// 256*(2e - agg) (128 B/node, 38.4 MB). Both L2-resident during edge phase.
__device__ uint4 g_embf8[(size_t)N_NODES * 4];
__device__ uint4 g_acc  [(size_t)N_NODES * 8];
__device__ int   g_identity;

__device__ __forceinline__ float sigf_exact(float x) {
    return 1.0f / (1.0f + __expf(-x));
}
// Odd-polynomial sigmoid: rel err < 3e-4 for |t| <= 1; exact fallback beyond.
__device__ __forceinline__ float sigf(float t) {
    if (__builtin_expect(fabsf(t) < 1.0f, 1)) {
        float t2 = t * t;
        float p  = fmaf(t2, 1.0f / 480.0f, -1.0f / 48.0f);
        p        = fmaf(t2, p, 0.25f);
        return fmaf(t, p, 0.5f);
    }
    return sigf_exact(t);
}

// pack two f32 into e4m3x2: byte0 = lo, byte1 = hi
__device__ __forceinline__ unsigned short f32x2_to_e4m3x2(float lo, float hi) {
    unsigned short r;
    asm("cvt.rn.satfinite.e4m3x2.f32 %0, %1, %2;" : "=h"(r) : "f"(hi), "f"(lo));
    return r;
}
// unpack e4m3x2 -> half2 (lane order preserved)
__device__ __forceinline__ unsigned e4m3x2_to_h2(unsigned v) {
    unsigned r;
    asm("{ .reg .b16 t; cvt.u16.u32 t, %1; cvt.rn.f16x2.e4m3x2 %0, t; }"
        : "=r"(r) : "r"(v));
    return r;
}
__device__ __forceinline__ unsigned h2_bits(__half2 h) {
    return *reinterpret_cast<unsigned*>(&h);
}
__device__ __forceinline__ unsigned hmul2u(unsigned a, unsigned b) {
    __half2 pa = *reinterpret_cast<__half2*>(&a);
    __half2 pb = *reinterpret_cast<__half2*>(&b);
    __half2 r = __hmul2(pa, pb);
    return h2_bits(r);
}
__device__ __forceinline__ float2 h2_to_f2(unsigned u) {
    __half2 p = *reinterpret_cast<__half2*>(&u);
    return __half22float2(p);
}

// ---------------------------------------------------------------------------
// Seed: out[n,0:64] = emb (f32); g_embf8[n] = fp8(emb*256);
// g_acc[n] = half(512*emb). 8 threads/node. Last block checks filt == I.
// ---------------------------------------------------------------------------
__global__ void seed_kernel(const float4* __restrict__ ue4,
                            const float4* __restrict__ ie4,
                            const float*  __restrict__ filt,
                            float4*       __restrict__ out4) {
    if (blockIdx.x == gridDim.x - 1) {
        __shared__ int ok;
        if (threadIdx.x == 0) ok = 1;
        __syncthreads();
        for (int i = threadIdx.x; i < DIM * DIM; i += blockDim.x) {
            int r = i >> 6, c = i & 63;
            float expect = (r == c) ? 1.0f : 0.0f;
            if (filt[i] != expect) atomicAnd(&ok, 0);
        }
        __syncthreads();
        if (threadIdx.x == 0) g_identity = ok;
        return;
    }
    unsigned idx = blockIdx.x * blockDim.x + threadIdx.x;
    unsigned n = idx >> 3;
    unsigned c = idx & 7u;
    if (n >= (unsigned)N_NODES) return;

    const float4* src = (n < N_USERS) ? (ue4 + (size_t)n * 16)
                                      : (ie4 + (size_t)(n - N_USERS) * 16);
    float4 e0 = __ldg(src + 2 * c);
    float4 e1 = __ldg(src + 2 * c + 1);

    // exact f32 emb half of output
    out4[(size_t)n * 32 + 2 * c]     = e0;
    out4[(size_t)n * 32 + 2 * c + 1] = e1;

    // fp8 copy (scaled)
    unsigned short s0 = f32x2_to_e4m3x2(e0.x * SCALE, e0.y * SCALE);
    unsigned short s1 = f32x2_to_e4m3x2(e0.z * SCALE, e0.w * SCALE);
    unsigned short s2 = f32x2_to_e4m3x2(e1.x * SCALE, e1.y * SCALE);
    unsigned short s3 = f32x2_to_e4m3x2(e1.z * SCALE, e1.w * SCALE);
    uint2 f8;
    f8.x = (unsigned)s0 | ((unsigned)s1 << 16);
    f8.y = (unsigned)s2 | ((unsigned)s3 << 16);
    reinterpret_cast<uint2*>(g_embf8)[(size_t)n * 8 + c] = f8;

    // half accumulator seeded with 2*e*SCALE
    uint4 av;
    av.x = h2_bits(__floats2half2_rn(512.f * e0.x, 512.f * e0.y));
    av.y = h2_bits(__floats2half2_rn(512.f * e0.z, 512.f * e0.w));
    av.z = h2_bits(__floats2half2_rn(512.f * e1.x, 512.f * e1.y));
    av.w = h2_bits(__floats2half2_rn(512.f * e1.z, 512.f * e1.w));
    g_acc[(size_t)n * 8 + c] = av;
}

// ---------------------------------------------------------------------------
// Edge scatter: acc[row] -= val * embf8[col]  (f16x2 vector L2 reduction)
// 4 threads/edge; each thread: 16B fp8 gather -> 32B of half RED.
// ---------------------------------------------------------------------------
__global__ void edge_kernel(const int*   __restrict__ rows,
                            const int*   __restrict__ cols,
                            const float* __restrict__ vals) {
    unsigned idx = blockIdx.x * blockDim.x + threadIdx.x;
    if (idx >= (unsigned)N_EDGES * 4u) return;
    unsigned e = idx >> 2;
    unsigned c = idx & 3u;

    int   col = __ldg(cols + e);
    int   row = __ldg(rows + e);
    float v   = __ldg(vals + e);
    unsigned vv = h2_bits(__float2half2_rn(-v));   // negated: acc = 2e - agg

    uint4 x = __ldg(&g_embf8[(size_t)col * 4 + c]);  // 16 fp8 values

    unsigned h0 = hmul2u(e4m3x2_to_h2(x.x),        vv);
    unsigned h1 = hmul2u(e4m3x2_to_h2(x.x >> 16),  vv);
    unsigned h2 = hmul2u(e4m3x2_to_h2(x.y),        vv);
    unsigned h3 = hmul2u(e4m3x2_to_h2(x.y >> 16),  vv);
    unsigned h4 = hmul2u(e4m3x2_to_h2(x.z),        vv);
    unsigned h5 = hmul2u(e4m3x2_to_h2(x.z >> 16),  vv);
    unsigned h6 = hmul2u(e4m3x2_to_h2(x.w),        vv);
    unsigned h7 = hmul2u(e4m3x2_to_h2(x.w >> 16),  vv);

    uint4* dst = &g_acc[(size_t)row * 8 + 2 * c];
    asm volatile("red.global.add.noftz.v4.f16x2 [%0], {%1, %2, %3, %4};"
                 :: "l"(dst), "r"(h0), "r"(h1), "r"(h2), "r"(h3) : "memory");
    asm volatile("red.global.add.noftz.v4.f16x2 [%0], {%1, %2, %3, %4};"
                 :: "l"(dst + 1), "r"(h4), "r"(h5), "r"(h6), "r"(h7) : "memory");
}

// ---------------------------------------------------------------------------
// Epilogue: acc holds 256*(2e - agg) in half. out[n,64:128] = sigmoid(t)
// (polynomial) or sigmoid(t @ filt) fallback. 8 threads/node; blockDim 256.
// ---------------------------------------------------------------------------
__global__ void epi_kernel(const float* __restrict__ filt,
                           float4*      __restrict__ out4) {
    unsigned idx = blockIdx.x * blockDim.x + threadIdx.x;
    unsigned n = idx >> 3;
    unsigned c = idx & 7u;
    bool active = (n < (unsigned)N_NODES);

    uint4 a = make_uint4(0, 0, 0, 0);
    if (active) a = g_acc[(size_t)n * 8 + c];
    float2 t0 = h2_to_f2(a.x);
    float2 t1 = h2_to_f2(a.y);
    float2 t2 = h2_to_f2(a.z);
    float2 t3 = h2_to_f2(a.w);
    t0.x *= INV_SCALE; t0.y *= INV_SCALE;
    t1.x *= INV_SCALE; t1.y *= INV_SCALE;
    t2.x *= INV_SCALE; t2.y *= INV_SCALE;
    t3.x *= INV_SCALE; t3.y *= INV_SCALE;

    if (g_identity) {
        if (active) {
            float4 h0 = make_float4(sigf(t0.x), sigf(t0.y), sigf(t1.x), sigf(t1.y));
            float4 h1 = make_float4(sigf(t2.x), sigf(t2.y), sigf(t3.x), sigf(t3.y));
            out4[(size_t)n * 32 + 16 + 2 * c]     = h0;
            out4[(size_t)n * 32 + 16 + 2 * c + 1] = h1;
        }
    } else {
        __shared__ float ts[32][DIM];
        unsigned ln = threadIdx.x >> 3;
        float* tr = ts[ln] + c * 8;
        tr[0] = t0.x; tr[1] = t0.y; tr[2] = t1.x; tr[3] = t1.y;
        tr[4] = t2.x; tr[5] = t2.y; tr[6] = t3.x; tr[7] = t3.y;
        __syncthreads();
        if (active) {
            const float* trow = ts[ln];
            float s[8] = {0.f};
            #pragma unroll 8
            for (int k = 0; k < DIM; k++) {
                float tk = trow[k];
                const float* frow = filt + (size_t)k * DIM + c * 8;
                #pragma unroll
                for (int j = 0; j < 8; j++) s[j] += tk * frow[j];
            }
            float4 h0 = make_float4(sigf_exact(s[0]), sigf_exact(s[1]),
                                    sigf_exact(s[2]), sigf_exact(s[3]));
            float4 h1 = make_float4(sigf_exact(s[4]), sigf_exact(s[5]),
                                    sigf_exact(s[6]), sigf_exact(s[7]));
            out4[(size_t)n * 32 + 16 + 2 * c]     = h0;
            out4[(size_t)n * 32 + 16 + 2 * c + 1] = h1;
        }
    }
}

// ---------------------------------------------------------------------------
// Launch (single stream)
// ---------------------------------------------------------------------------
extern "C" void kernel_launch(void* const* d_in, const int* in_sizes, int n_in,
                              void* d_out, int out_size) {
    const int*   rows = (const int*)  d_in[0];
    const int*   cols = (const int*)  d_in[1];
    const float* vals = (const float*)d_in[2];
    const float* ue   = (const float*)d_in[3];
    const float* ie   = (const float*)d_in[4];
    const float* filt = (const float*)d_in[5];
    float4*      out4 = (float4*)d_out;

    const unsigned seed_threads = (unsigned)N_NODES * 8u;        // 2.4M
    const unsigned seed_blocks  = (seed_threads + 255) / 256;
    seed_kernel<<<seed_blocks + 1, 256>>>(
        (const float4*)ue, (const float4*)ie, filt, out4);

    const unsigned edge_threads = (unsigned)N_EDGES * 4u;        // 4.8M
    edge_kernel<<<(edge_threads + 255) / 256, 256>>>(rows, cols, vals);

    const unsigned epi_threads = (unsigned)N_NODES * 8u;         // 2.4M
    epi_kernel<<<(epi_threads + 255) / 256, 256>>>(filt, out4);
}

// round 9
// speedup vs baseline: 1.4370x; 1.0564x over previous
#include <cuda_runtime.h>
#include <cuda_fp16.h>
#include <cstddef>

#define N_USERS 200000
#define N_ITEMS 100000
#define N_NODES 300000
#define DIM     64
#define N_EDGES 1200000

#define SCALE     256.0f
#define INV_SCALE (1.0f / 256.0f)

#define SCAN_BLK 1024
#define NB_SCAN  ((N_NODES + SCAN_BLK - 1) / SCAN_BLK)   // 293
static_assert(NB_SCAN <= SCAN_BLK, "scan3 single-load prefix assumption");

// fp8(e4m3) copy of emb*256: 64 B/node (uint2 per 8 dims), 19.2 MB.
__device__ uint2 g_embf8[(size_t)N_NODES * 8];
// CSR: degree (zero-invariant across launches), offsets, block sums, buckets.
__device__ int   g_deg[N_NODES];
__device__ int   g_off[N_NODES + 1];
__device__ int   g_bsum[NB_SCAN];
__device__ uint2 g_edge[N_EDGES];     // {col, float bits of val}
__device__ int   g_identity;

__device__ __forceinline__ float sigf_exact(float x) {
    return 1.0f / (1.0f + __expf(-x));
}
// Odd-polynomial sigmoid: rel err < 3e-4 for |t| <= 1; exact fallback beyond.
__device__ __forceinline__ float sigf(float t) {
    if (__builtin_expect(fabsf(t) < 1.0f, 1)) {
        float t2 = t * t;
        float p  = fmaf(t2, 1.0f / 480.0f, -1.0f / 48.0f);
        p        = fmaf(t2, p, 0.25f);
        return fmaf(t, p, 0.5f);
    }
    return sigf_exact(t);
}
__device__ __forceinline__ unsigned short f32x2_to_e4m3x2(float lo, float hi) {
    unsigned short r;
    asm("cvt.rn.satfinite.e4m3x2.f32 %0, %1, %2;" : "=h"(r) : "f"(hi), "f"(lo));
    return r;
}
__device__ __forceinline__ unsigned e4m3x2_to_h2(unsigned v) {
    unsigned r;
    asm("{ .reg .b16 t; cvt.u16.u32 t, %1; cvt.rn.f16x2.e4m3x2 %0, t; }"
        : "=r"(r) : "r"(v));
    return r;
}
__device__ __forceinline__ float2 h2_to_f2(unsigned u) {
    __half2 p = *reinterpret_cast<__half2*>(&u);
    return __half22float2(p);
}
// unpack 8 fp8 (uint2) -> 8 floats (scaled domain)
__device__ __forceinline__ void fp8x8_to_f32(uint2 b, float* f) {
    float2 q;
    q = h2_to_f2(e4m3x2_to_h2(b.x));       f[0] = q.x; f[1] = q.y;
    q = h2_to_f2(e4m3x2_to_h2(b.x >> 16)); f[2] = q.x; f[3] = q.y;
    q = h2_to_f2(e4m3x2_to_h2(b.y));       f[4] = q.x; f[5] = q.y;
    q = h2_to_f2(e4m3x2_to_h2(b.y >> 16)); f[6] = q.x; f[7] = q.y;
}

// ---------------------------------------------------------------------------
// Seed: out[n,0:64] = emb (f32); g_embf8[n] = fp8(emb*256).
// 8 threads/node. Last block checks filt == I.
// ---------------------------------------------------------------------------
__global__ void seed_kernel(const float4* __restrict__ ue4,
                            const float4* __restrict__ ie4,
                            const float*  __restrict__ filt,
                            float4*       __restrict__ out4) {
    if (blockIdx.x == gridDim.x - 1) {
        __shared__ int ok;
        if (threadIdx.x == 0) ok = 1;
        __syncthreads();
        for (int i = threadIdx.x; i < DIM * DIM; i += blockDim.x) {
            int r = i >> 6, c = i & 63;
            float expect = (r == c) ? 1.0f : 0.0f;
            if (filt[i] != expect) atomicAnd(&ok, 0);
        }
        __syncthreads();
        if (threadIdx.x == 0) g_identity = ok;
        return;
    }
    unsigned idx = blockIdx.x * blockDim.x + threadIdx.x;
    unsigned n = idx >> 3;
    unsigned c = idx & 7u;
    if (n >= (unsigned)N_NODES) return;

    const float4* src = (n < N_USERS) ? (ue4 + (size_t)n * 16)
                                      : (ie4 + (size_t)(n - N_USERS) * 16);
    float4 e0 = __ldg(src + 2 * c);
    float4 e1 = __ldg(src + 2 * c + 1);

    out4[(size_t)n * 32 + 2 * c]     = e0;
    out4[(size_t)n * 32 + 2 * c + 1] = e1;

    unsigned short s0 = f32x2_to_e4m3x2(e0.x * SCALE, e0.y * SCALE);
    unsigned short s1 = f32x2_to_e4m3x2(e0.z * SCALE, e0.w * SCALE);
    unsigned short s2 = f32x2_to_e4m3x2(e1.x * SCALE, e1.y * SCALE);
    unsigned short s3 = f32x2_to_e4m3x2(e1.z * SCALE, e1.w * SCALE);
    uint2 f8;
    f8.x = (unsigned)s0 | ((unsigned)s1 << 16);
    f8.y = (unsigned)s2 | ((unsigned)s3 << 16);
    g_embf8[(size_t)n * 8 + c] = f8;
}

// ---------------------------------------------------------------------------
// Histogram of destination rows. g_deg is all-zero at entry (zero-initialized
// device global; k_scatter's atomicSub drains it back to zero every launch).
// ---------------------------------------------------------------------------
__global__ void k_hist(const int* __restrict__ rows) {
    unsigned e = blockIdx.x * blockDim.x + threadIdx.x;
    if (e < (unsigned)N_EDGES) atomicAdd(&g_deg[__ldg(rows + e)], 1);
}

// ---------------------------------------------------------------------------
// Scan pass 1: per-block exclusive scan of deg -> off, block totals -> bsum
// ---------------------------------------------------------------------------
__global__ void k_scan1() {
    __shared__ int wsum[32];
    int i = blockIdx.x * SCAN_BLK + threadIdx.x;
    int v = (i < N_NODES) ? g_deg[i] : 0;
    int lane = threadIdx.x & 31, wid = threadIdx.x >> 5;

    int x = v;
    #pragma unroll
    for (int d = 1; d < 32; d <<= 1) {
        int y = __shfl_up_sync(0xffffffffu, x, d);
        if (lane >= d) x += y;
    }
    if (lane == 31) wsum[wid] = x;
    __syncthreads();
    if (wid == 0) {
        int s = wsum[lane];
        #pragma unroll
        for (int d = 1; d < 32; d <<= 1) {
            int y = __shfl_up_sync(0xffffffffu, s, d);
            if (lane >= d) s += y;
        }
        wsum[lane] = s;
    }
    __syncthreads();
    int warpoff = (wid == 0) ? 0 : wsum[wid - 1];
    if (i < N_NODES) g_off[i] = warpoff + x - v;
    if (threadIdx.x == SCAN_BLK - 1) g_bsum[blockIdx.x] = warpoff + x;
}

// ---------------------------------------------------------------------------
// Scan pass 2 (fused): each block reduces bsum[0..bid) and adds the prefix
// to its off slice. Also writes off[N] = N_EDGES.
// ---------------------------------------------------------------------------
__global__ void k_scan3() {
    __shared__ int wsum[32];
    int tid = threadIdx.x;
    int b = blockIdx.x;
    int s = (tid < b) ? g_bsum[tid] : 0;      // b < 1024, one load covers all
    #pragma unroll
    for (int d = 16; d; d >>= 1) s += __shfl_down_sync(0xffffffffu, s, d);
    if ((tid & 31) == 0) wsum[tid >> 5] = s;
    __syncthreads();
    if (tid < 32) {
        int v = wsum[tid];
        #pragma unroll
        for (int d = 16; d; d >>= 1) v += __shfl_down_sync(0xffffffffu, v, d);
        if (tid == 0) wsum[0] = v;
    }
    __syncthreads();
    int pre = wsum[0];
    int i = b * SCAN_BLK + tid;
    if (i < N_NODES) g_off[i] += pre;
    if (i == N_NODES) g_off[N_NODES] = N_EDGES;
}

// ---------------------------------------------------------------------------
// Scatter: bucket edges by row. atomicSub drains g_deg back to zero.
// ---------------------------------------------------------------------------
__global__ void k_scatter(const int*   __restrict__ rows,
                          const int*   __restrict__ cols,
                          const float* __restrict__ vals) {
    unsigned e = blockIdx.x * blockDim.x + threadIdx.x;
    if (e >= (unsigned)N_EDGES) return;
    int r = __ldg(rows + e);
    int pos = __ldg(&g_off[r]) + atomicSub(&g_deg[r], 1) - 1;
    uint2 pk;
    pk.x = (unsigned)__ldg(cols + e);
    pk.y = __float_as_uint(__ldg(vals + e));
    g_edge[pos] = pk;
}

// ---------------------------------------------------------------------------
// Consume + epilogue fused: 8 threads/node, f32 register accumulation,
// zero atomics. out[n,64:128] = sigmoid(2e - sum val*emb[col]) (poly),
// or the filt-matmul fallback. blockDim 256 (32 nodes/block).
// ---------------------------------------------------------------------------
__global__ void k_consume(const float* __restrict__ filt,
                          float4*      __restrict__ out4) {
    unsigned idx = blockIdx.x * blockDim.x + threadIdx.x;
    unsigned n = idx >> 3;
    unsigned c = idx & 7u;
    bool active = (n < (unsigned)N_NODES);

    float acc[8] = {0.f, 0.f, 0.f, 0.f, 0.f, 0.f, 0.f, 0.f};
    if (active) {
        // seed with 2*E (scaled domain)
        uint2 eb = g_embf8[(size_t)n * 8 + c];
        float E[8];
        fp8x8_to_f32(eb, E);
        #pragma unroll
        for (int j = 0; j < 8; j++) acc[j] = 2.0f * E[j];

        int beg = __ldg(&g_off[n]);
        int end = __ldg(&g_off[n + 1]);
        for (int p = beg; p < end; ++p) {
            uint2 pk = __ldg(&g_edge[p]);
            float v = __uint_as_float(pk.y);
            uint2 xb = __ldg(&g_embf8[(size_t)pk.x * 8 + c]);
            float x[8];
            fp8x8_to_f32(xb, x);
            #pragma unroll
            for (int j = 0; j < 8; j++) acc[j] = fmaf(-v, x[j], acc[j]);
        }
    }

    float t[8];
    #pragma unroll
    for (int j = 0; j < 8; j++) t[j] = acc[j] * INV_SCALE;

    if (g_identity) {
        if (active) {
            float4 h0 = make_float4(sigf(t[0]), sigf(t[1]), sigf(t[2]), sigf(t[3]));
            float4 h1 = make_float4(sigf(t[4]), sigf(t[5]), sigf(t[6]), sigf(t[7]));
            out4[(size_t)n * 32 + 16 + 2 * c]     = h0;
            out4[(size_t)n * 32 + 16 + 2 * c + 1] = h1;
        }
    } else {
        __shared__ float ts[32][DIM];
        unsigned ln = threadIdx.x >> 3;
        float* tr = ts[ln] + c * 8;
        #pragma unroll
        for (int j = 0; j < 8; j++) tr[j] = t[j];
        __syncthreads();
        if (active) {
            const float* trow = ts[ln];
            float s[8] = {0.f};
            #pragma unroll 8
            for (int k = 0; k < DIM; k++) {
                float tk = trow[k];
                const float* frow = filt + (size_t)k * DIM + c * 8;
                #pragma unroll
                for (int j = 0; j < 8; j++) s[j] += tk * frow[j];
            }
            float4 h0 = make_float4(sigf_exact(s[0]), sigf_exact(s[1]),
                                    sigf_exact(s[2]), sigf_exact(s[3]));
            float4 h1 = make_float4(sigf_exact(s[4]), sigf_exact(s[5]),
                                    sigf_exact(s[6]), sigf_exact(s[7]));
            out4[(size_t)n * 32 + 16 + 2 * c]     = h0;
            out4[(size_t)n * 32 + 16 + 2 * c + 1] = h1;
        }
    }
}

// ---------------------------------------------------------------------------
// Launch
// ---------------------------------------------------------------------------
extern "C" void kernel_launch(void* const* d_in, const int* in_sizes, int n_in,
                              void* d_out, int out_size) {
    const int*   rows = (const int*)  d_in[0];
    const int*   cols = (const int*)  d_in[1];
    const float* vals = (const float*)d_in[2];
    const float* ue   = (const float*)d_in[3];
    const float* ie   = (const float*)d_in[4];
    const float* filt = (const float*)d_in[5];
    float4*      out4 = (float4*)d_out;

    const unsigned seed_threads = (unsigned)N_NODES * 8u;        // 2.4M
    const unsigned seed_blocks  = (seed_threads + 255) / 256;
    seed_kernel<<<seed_blocks + 1, 256>>>(
        (const float4*)ue, (const float4*)ie, filt, out4);

    const unsigned edge_blocks = (N_EDGES + 255) / 256;          // 4688
    k_hist<<<edge_blocks, 256>>>(rows);

    k_scan1<<<NB_SCAN, SCAN_BLK>>>();
    k_scan3<<<NB_SCAN, SCAN_BLK>>>();

    k_scatter<<<edge_blocks, 256>>>(rows, cols, vals);

    const unsigned cons_threads = (unsigned)N_NODES * 8u;        // 2.4M
    k_consume<<<(cons_threads + 255) / 256, 256>>>(filt, out4);
}